// round 2
// baseline (speedup 1.0000x reference)
#include <cuda_runtime.h>
#include <math.h>

// Problem constants
#define BB 8
#define LL 2048
#define DD 1024
#define ZZ 128
#define HH 2048
#define GG 32
#define MP 2048
#define BW 4224   // Z + H + 2D

// ---------------- scratch (device globals; no cudaMalloc allowed) ----------------
__device__ __align__(16) float g_xn[BB*LL*DD];     //  64 MB
__device__ __align__(16) float g_s1[BB*LL*GG];     //   2 MB
__device__ __align__(16) float g_s2[BB*LL*GG];     //   2 MB
__device__ __align__(16) float g_v [BB*LL*HH];     // 128 MB
__device__ __align__(16) float g_mx[BB*LL*DD];     //  64 MB
__device__ __align__(16) float g_base[BB*LL*BW];   // 277 MB
__device__ __align__(16) float g_S [BB*LL*LL];     // 134 MB
__device__ __align__(16) float g_hr[BB*LL*HH];     // 128 MB

__device__ __forceinline__ float sigm(float x){ return 1.f/(1.f+__expf(-x)); }
__device__ __forceinline__ float siluf(float x){ return x/(1.f+__expf(-x)); }
__device__ __forceinline__ float warpMax(float v){
  #pragma unroll
  for(int o=16;o>0;o>>=1) v=fmaxf(v,__shfl_xor_sync(0xffffffffu,v,o));
  return v;
}
__device__ __forceinline__ float warpSum(float v){
  #pragma unroll
  for(int o=16;o>0;o>>=1) v+=__shfl_xor_sync(0xffffffffu,v,o);
  return v;
}

// ======================= timestep_norm: group sums + scan =======================
// one block per (b,g); 256 threads * 8 timesteps each; block-scan of cumsums
__global__ void __launch_bounds__(256) tn_scan(const float* __restrict__ x){
  int bg = blockIdx.x; int b = bg >> 5; int g = bg & 31;
  int t = threadIdx.x;
  float c1[8], c2[8];
  float r1 = 0.f, r2 = 0.f;
  const float* xb = x + (size_t)b*LL*DD + g*32;
  #pragma unroll
  for(int i=0;i<8;i++){
    int l = t*8 + i;
    const float4* q = (const float4*)(xb + (size_t)l*DD);
    float a1=0.f, a2=0.f;
    #pragma unroll
    for(int c=0;c<8;c++){
      float4 f = q[c];
      a1 += f.x+f.y+f.z+f.w;
      a2 += f.x*f.x+f.y*f.y+f.z*f.z+f.w*f.w;
    }
    r1 += a1; r2 += a2;
    c1[i] = r1; c2[i] = r2;
  }
  __shared__ float sm1[256], sm2[256];
  sm1[t]=r1; sm2[t]=r2;
  __syncthreads();
  for(int off=1; off<256; off<<=1){
    float a1=0.f, a2=0.f;
    if(t>=off){ a1=sm1[t-off]; a2=sm2[t-off]; }
    __syncthreads();
    sm1[t]+=a1; sm2[t]+=a2;
    __syncthreads();
  }
  float p1 = (t>0)? sm1[t-1] : 0.f;
  float p2 = (t>0)? sm2[t-1] : 0.f;
  #pragma unroll
  for(int i=0;i<8;i++){
    int l = t*8 + i;
    g_s1[((size_t)b*LL + l)*GG + g] = p1 + c1[i];
    g_s2[((size_t)b*LL + l)*GG + g] = p2 + c2[i];
  }
}

// elementwise normalize -> g_xn
__global__ void __launch_bounds__(256) tn_norm_k(
    const float* __restrict__ x, const float* __restrict__ pm,
    const float* __restrict__ plv, const float* __restrict__ w,
    const float* __restrict__ bias){
  int idx = blockIdx.x*256 + threadIdx.x;
  int d  = idx & (DD-1);
  int bl = idx >> 10;          // b*L + l
  int l  = bl & (LL-1);
  int g  = d >> 5;
  float s1 = g_s1[(size_t)bl*GG + g];
  float s2 = g_s2[(size_t)bl*GG + g];
  float cnt = 2.0f + 32.0f*(float)(l+1);
  float pmg = pm[g];
  float pv  = expf(plv[g]);
  float mean = (2.0f*pmg + s1)/cnt;
  float var  = (2.0f*(pv + pmg*pmg) + s2)/cnt - mean*mean;
  float xv = x[idx];
  g_xn[idx] = (xv - mean)*rsqrtf(var + 1e-5f)*w[d] + bias[d];
}

// ======================= multihead EMA as 16-state linear scan =======================
// kern[d,l] = sum_n (p*beta)_n q_n^l (gamma/sqrt(N))_n  ->  s_n(l)=q s_n(l-1)+pb x(l)
__global__ void __launch_bounds__(64) ema_k(
    const float* __restrict__ delta, const float* __restrict__ alpha,
    const float* __restrict__ ebeta, const float* __restrict__ egam,
    const float* __restrict__ omega){
  int b = blockIdx.x >> 4;
  int d = ((blockIdx.x & 15) << 6) + threadIdx.x;
  float q[16], pb[16], gs[16], s[16];
  #pragma unroll
  for(int n=0;n<16;n++){
    float p = 1.f/(1.f+expf(-delta[d*16+n]));
    float a = 1.f/(1.f+expf(-alpha[d*16+n]));
    q[n]  = 1.f - p*a;
    pb[n] = p*ebeta[d*16+n];
    gs[n] = egam[d*16+n]*0.25f;   // 1/sqrt(16)
    s[n]  = 0.f;
  }
  float om = omega[d];
  const float* xp = g_xn + (size_t)b*LL*DD + d;
  float*       op = g_mx + (size_t)b*LL*DD + d;
  for(int l=0;l<LL;l++){
    float xv = xp[(size_t)l*DD];
    float o0 = om*xv, o1=0.f, o2=0.f, o3=0.f;
    #pragma unroll
    for(int n=0;n<16;n+=4){
      s[n+0] = q[n+0]*s[n+0] + pb[n+0]*xv; o0 += gs[n+0]*s[n+0];
      s[n+1] = q[n+1]*s[n+1] + pb[n+1]*xv; o1 += gs[n+1]*s[n+1];
      s[n+2] = q[n+2]*s[n+2] + pb[n+2]*xv; o2 += gs[n+2]*s[n+2];
      s[n+3] = q[n+3]*s[n+3] + pb[n+3]*xv; o3 += gs[n+3]*s[n+3];
    }
    op[(size_t)l*DD] = (o0+o1)+(o2+o3);
  }
}

// ======================= RMS norm (in place on g_mx) =======================
__global__ void __launch_bounds__(256) rms_norm(const float* __restrict__ w){
  int row = blockIdx.x;
  float* p = g_mx + (size_t)row*DD;
  int t = threadIdx.x;
  float v[4]; float ss = 0.f;
  #pragma unroll
  for(int j=0;j<4;j++){ v[j] = p[t + 256*j]; ss += v[j]*v[j]; }
  __shared__ float red[8];
  ss = warpSum(ss);
  if((t&31)==0) red[t>>5] = ss;
  __syncthreads();
  if(t<32){
    float a = (t<8)? red[t] : 0.f;
    a = warpSum(a);
    if(t==0) red[0] = a;
  }
  __syncthreads();
  float sc = rsqrtf(red[0]*(1.0f/DD) + 1e-5f);
  #pragma unroll
  for(int j=0;j<4;j++) p[t+256*j] = v[j]*sc*w[t+256*j];
}

// ======================= SGEMM (NT): C = act(A @ W^T + bias) =======================
// BM=BN=128, BK=16, 256 threads, 8x8 microtile
template<int ACT> // 0: none, 1: silu
__global__ void __launch_bounds__(256) sgemm_nt(
    const float* __restrict__ A, const float* __restrict__ W,
    const float* __restrict__ bias, float* __restrict__ C,
    int M, int N, int K){
  __shared__ __align__(16) float As[16][128];
  __shared__ __align__(16) float Bs[16][128];
  int bm = blockIdx.y*128, bn = blockIdx.x*128;
  int tid = threadIdx.x;
  int lr  = tid >> 1;          // 0..127
  int lc8 = (tid & 1) << 3;    // 0 or 8
  int ty  = tid >> 4, tx = tid & 15;
  float acc[8][8] = {};
  const float* Ap = A + (size_t)(bm+lr)*K + lc8;
  const float* Wp = W + (size_t)(bn+lr)*K + lc8;
  for(int k0=0;k0<K;k0+=16){
    float4 a0 = *(const float4*)(Ap + k0);
    float4 a1 = *(const float4*)(Ap + k0 + 4);
    float4 b0 = *(const float4*)(Wp + k0);
    float4 b1 = *(const float4*)(Wp + k0 + 4);
    As[lc8+0][lr]=a0.x; As[lc8+1][lr]=a0.y; As[lc8+2][lr]=a0.z; As[lc8+3][lr]=a0.w;
    As[lc8+4][lr]=a1.x; As[lc8+5][lr]=a1.y; As[lc8+6][lr]=a1.z; As[lc8+7][lr]=a1.w;
    Bs[lc8+0][lr]=b0.x; Bs[lc8+1][lr]=b0.y; Bs[lc8+2][lr]=b0.z; Bs[lc8+3][lr]=b0.w;
    Bs[lc8+4][lr]=b1.x; Bs[lc8+5][lr]=b1.y; Bs[lc8+6][lr]=b1.z; Bs[lc8+7][lr]=b1.w;
    __syncthreads();
    #pragma unroll
    for(int kk=0;kk<16;kk++){
      float a[8], b[8];
      *(float4*)&a[0] = *(const float4*)&As[kk][ty<<3];
      *(float4*)&a[4] = *(const float4*)&As[kk][(ty<<3)+4];
      *(float4*)&b[0] = *(const float4*)&Bs[kk][tx<<3];
      *(float4*)&b[4] = *(const float4*)&Bs[kk][(tx<<3)+4];
      #pragma unroll
      for(int i=0;i<8;i++)
        #pragma unroll
        for(int j=0;j<8;j++) acc[i][j] += a[i]*b[j];
    }
    __syncthreads();
  }
  #pragma unroll
  for(int i=0;i<8;i++){
    int row = bm + (ty<<3) + i;
    #pragma unroll
    for(int j=0;j<8;j++){
      int col = bn + (tx<<3) + j;
      float v = acc[i][j] + bias[col];
      if(ACT==1) v = v/(1.f+__expf(-v));
      C[(size_t)row*N + col] = v;
    }
  }
}

// ======================= QK^T GEMM (q/k transforms fused in loads) =======================
__global__ void __launch_bounds__(256) qk_gemm(
    const float* __restrict__ qkg, const float* __restrict__ qkb,
    const float* __restrict__ relb){
  __shared__ __align__(16) float Qs[16][128];
  __shared__ __align__(16) float Ks[16][128];
  int bz = blockIdx.z;
  int bm = blockIdx.y*128, bn = blockIdx.x*128;
  int tid = threadIdx.x;
  int lr  = tid >> 1;
  int lc8 = (tid & 1) << 3;
  int ty  = tid >> 4, tx = tid & 15;
  const float RSQZ = 0.0883883476483184f; // Z^-0.5
  float acc[8][8] = {};
  const float* Qp = g_base + ((size_t)(bz*LL + bm + lr))*BW + DD + lc8;
  const float* Kp = g_base + ((size_t)(bz*LL + bn + lr))*BW + DD + lc8;
  for(int k0=0;k0<ZZ;k0+=16){
    float4 a0 = *(const float4*)(Qp + k0);
    float4 a1 = *(const float4*)(Qp + k0 + 4);
    float4 b0 = *(const float4*)(Kp + k0);
    float4 b1 = *(const float4*)(Kp + k0 + 4);
    float av[8] = {a0.x,a0.y,a0.z,a0.w,a1.x,a1.y,a1.z,a1.w};
    float bv[8] = {b0.x,b0.y,b0.z,b0.w,b1.x,b1.y,b1.z,b1.w};
    #pragma unroll
    for(int c=0;c<8;c++){
      int z = k0 + lc8 + c;
      float zq = siluf(av[c]);
      float zk = siluf(bv[c]);
      Qs[lc8+c][lr] = (zq*qkg[z]     + qkb[z])     * RSQZ;
      Ks[lc8+c][lr] = (zk*qkg[ZZ+z]  + qkb[ZZ+z]);
    }
    __syncthreads();
    #pragma unroll
    for(int kk=0;kk<16;kk++){
      float a[8], b[8];
      *(float4*)&a[0] = *(const float4*)&Qs[kk][ty<<3];
      *(float4*)&a[4] = *(const float4*)&Qs[kk][(ty<<3)+4];
      *(float4*)&b[0] = *(const float4*)&Ks[kk][tx<<3];
      *(float4*)&b[4] = *(const float4*)&Ks[kk][(tx<<3)+4];
      #pragma unroll
      for(int i=0;i<8;i++)
        #pragma unroll
        for(int j=0;j<8;j++) acc[i][j] += a[i]*b[j];
    }
    __syncthreads();
  }
  #pragma unroll
  for(int i=0;i<8;i++){
    int row = bm + (ty<<3) + i;
    float* sp = g_S + ((size_t)(bz*LL + row))*LL;
    #pragma unroll
    for(int j=0;j<8;j++){
      int col = bn + (tx<<3) + j;
      float v = acc[i][j] + relb[MP-1 + col - row];
      if(col > row) v = -1e30f;
      sp[col] = v;
    }
  }
}

// ======================= row softmax on g_S =======================
__global__ void __launch_bounds__(256) softmax_rows(){
  int row = blockIdx.x;       // b*L + i
  float* p = g_S + (size_t)row*LL;
  int t = threadIdx.x;
  float v[8];
  float m = -3.0e38f;
  #pragma unroll
  for(int j=0;j<8;j++){ v[j] = p[t + 256*j]; m = fmaxf(m, v[j]); }
  __shared__ float red[8];
  m = warpMax(m);
  if((t&31)==0) red[t>>5] = m;
  __syncthreads();
  if(t<32){
    float a = (t<8)? red[t] : -3.0e38f;
    a = warpMax(a);
    if(t==0) red[0] = a;
  }
  __syncthreads();
  m = red[0];
  __syncthreads();
  float s = 0.f;
  #pragma unroll
  for(int j=0;j<8;j++){ v[j] = __expf(v[j]-m); s += v[j]; }
  s = warpSum(s);
  if((t&31)==0) red[t>>5] = s;
  __syncthreads();
  if(t<32){
    float a = (t<8)? red[t] : 0.f;
    a = warpSum(a);
    if(t==0) red[0] = a;
  }
  __syncthreads();
  float inv = 1.f/red[0];
  #pragma unroll
  for(int j=0;j<8;j++) p[t + 256*j] = v[j]*inv;
}

// ======================= attn @ v (NN), epilogue x silu(r) =======================
__global__ void __launch_bounds__(256) av_gemm(){
  __shared__ __align__(16) float As[16][128];
  __shared__ __align__(16) float Bs[16][128];
  int bz = blockIdx.z;
  int bm = blockIdx.y*128, bn = blockIdx.x*128;
  int tid = threadIdx.x;
  int lr  = tid >> 1;
  int lc8 = (tid & 1) << 3;
  int vr  = tid >> 4;            // 0..15 (k row)
  int vc  = (tid & 15) << 3;     // col offset
  int ty  = tid >> 4, tx = tid & 15;
  float acc[8][8] = {};
  const float* Ap = g_S + ((size_t)(bz*LL + bm + lr))*LL + lc8;
  const float* Vp = g_v + (size_t)bz*LL*HH + bn + vc;
  for(int k0=0;k0<LL;k0+=16){
    float4 a0 = *(const float4*)(Ap + k0);
    float4 a1 = *(const float4*)(Ap + k0 + 4);
    float4 b0 = *(const float4*)(Vp + (size_t)(k0+vr)*HH);
    float4 b1 = *(const float4*)(Vp + (size_t)(k0+vr)*HH + 4);
    As[lc8+0][lr]=a0.x; As[lc8+1][lr]=a0.y; As[lc8+2][lr]=a0.z; As[lc8+3][lr]=a0.w;
    As[lc8+4][lr]=a1.x; As[lc8+5][lr]=a1.y; As[lc8+6][lr]=a1.z; As[lc8+7][lr]=a1.w;
    *(float4*)&Bs[vr][vc]   = b0;
    *(float4*)&Bs[vr][vc+4] = b1;
    __syncthreads();
    #pragma unroll
    for(int kk=0;kk<16;kk++){
      float a[8], b[8];
      *(float4*)&a[0] = *(const float4*)&As[kk][ty<<3];
      *(float4*)&a[4] = *(const float4*)&As[kk][(ty<<3)+4];
      *(float4*)&b[0] = *(const float4*)&Bs[kk][tx<<3];
      *(float4*)&b[4] = *(const float4*)&Bs[kk][(tx<<3)+4];
      #pragma unroll
      for(int i=0;i<8;i++)
        #pragma unroll
        for(int j=0;j<8;j++) acc[i][j] += a[i]*b[j];
    }
    __syncthreads();
  }
  #pragma unroll
  for(int i=0;i<8;i++){
    int row = bm + (ty<<3) + i;
    const float* br = g_base + ((size_t)(bz*LL + row))*BW + DD + ZZ;
    float* hp = g_hr + ((size_t)(bz*LL + row))*HH;
    #pragma unroll
    for(int j=0;j<8;j++){
      int col = bn + (tx<<3) + j;
      hp[col] = acc[i][j] * siluf(br[col]);
    }
  }
}

// ======================= final: (h*r)@Wh^T, gated output epilogue =======================
__global__ void __launch_bounds__(256) final_gemm(
    const float* __restrict__ Wh, const float* __restrict__ x,
    float* __restrict__ out){
  __shared__ __align__(16) float As[16][128];
  __shared__ __align__(16) float Bs[16][128];
  int bm = blockIdx.y*128, bn = blockIdx.x*128;
  int tid = threadIdx.x;
  int lr  = tid >> 1;
  int lc8 = (tid & 1) << 3;
  int ty  = tid >> 4, tx = tid & 15;
  float acc[8][8] = {};
  const float* Ap = g_hr + (size_t)(bm+lr)*HH + lc8;
  const float* Wp = Wh   + (size_t)(bn+lr)*HH + lc8;
  for(int k0=0;k0<HH;k0+=16){
    float4 a0 = *(const float4*)(Ap + k0);
    float4 a1 = *(const float4*)(Ap + k0 + 4);
    float4 b0 = *(const float4*)(Wp + k0);
    float4 b1 = *(const float4*)(Wp + k0 + 4);
    As[lc8+0][lr]=a0.x; As[lc8+1][lr]=a0.y; As[lc8+2][lr]=a0.z; As[lc8+3][lr]=a0.w;
    As[lc8+4][lr]=a1.x; As[lc8+5][lr]=a1.y; As[lc8+6][lr]=a1.z; As[lc8+7][lr]=a1.w;
    Bs[lc8+0][lr]=b0.x; Bs[lc8+1][lr]=b0.y; Bs[lc8+2][lr]=b0.z; Bs[lc8+3][lr]=b0.w;
    Bs[lc8+4][lr]=b1.x; Bs[lc8+5][lr]=b1.y; Bs[lc8+6][lr]=b1.z; Bs[lc8+7][lr]=b1.w;
    __syncthreads();
    #pragma unroll
    for(int kk=0;kk<16;kk++){
      float a[8], b[8];
      *(float4*)&a[0] = *(const float4*)&As[kk][ty<<3];
      *(float4*)&a[4] = *(const float4*)&As[kk][(ty<<3)+4];
      *(float4*)&b[0] = *(const float4*)&Bs[kk][tx<<3];
      *(float4*)&b[4] = *(const float4*)&Bs[kk][(tx<<3)+4];
      #pragma unroll
      for(int i=0;i<8;i++)
        #pragma unroll
        for(int j=0;j<8;j++) acc[i][j] += a[i]*b[j];
    }
    __syncthreads();
  }
  #pragma unroll
  for(int i=0;i<8;i++){
    int row = bm + (ty<<3) + i;   // b*L + l
    const float* br = g_base + (size_t)row*BW;
    const float* xr = x + (size_t)row*DD;
    float* op = out + (size_t)row*DD;
    #pragma unroll
    for(int j=0;j<8;j++){
      int col = bn + (tx<<3) + j;
      float t  = br[DD+ZZ+HH+col] + acc[i][j];
      t = t/(1.f+__expf(-t));               // silu(hx + h*r@Wh^T)
      float u  = 1.f/(1.f+__expf(-br[col])); // sigmoid gate
      float xv = xr[col];
      op[col] = xv + u*(t - xv);
    }
  }
}

// ======================= launch =======================
extern "C" void kernel_launch(void* const* d_in, const int* in_sizes, int n_in,
                              void* d_out, int out_size){
  (void)in_sizes; (void)n_in; (void)out_size;
  const float* x          = (const float*)d_in[0];
  const float* prior_mean = (const float*)d_in[1];
  const float* prior_logv = (const float*)d_in[2];
  const float* tn_weight  = (const float*)d_in[3];
  const float* tn_bias    = (const float*)d_in[4];
  const float* delta      = (const float*)d_in[5];
  const float* alpha      = (const float*)d_in[6];
  const float* ema_beta   = (const float*)d_in[7];
  const float* ema_gamma  = (const float*)d_in[8];
  const float* omega      = (const float*)d_in[9];
  const float* rms_weight = (const float*)d_in[10];
  const float* Wv         = (const float*)d_in[11];
  const float* bv         = (const float*)d_in[12];
  const float* Wmx        = (const float*)d_in[13];
  const float* bmx        = (const float*)d_in[14];
  const float* Wh         = (const float*)d_in[15];
  const float* qk_gamma   = (const float*)d_in[16];
  const float* qk_beta    = (const float*)d_in[17];
  const float* rel_bias   = (const float*)d_in[18];
  float* out = (float*)d_out;

  float *p_xn, *p_mx, *p_v, *p_base;
  cudaGetSymbolAddress((void**)&p_xn,   g_xn);
  cudaGetSymbolAddress((void**)&p_mx,   g_mx);
  cudaGetSymbolAddress((void**)&p_v,    g_v);
  cudaGetSymbolAddress((void**)&p_base, g_base);

  // 1) timestep norm
  tn_scan<<<BB*GG, 256>>>(x);
  tn_norm_k<<<(BB*LL*DD)/256, 256>>>(x, prior_mean, prior_logv, tn_weight, tn_bias);
  // 2) v = silu(xn @ Wv^T + bv)
  sgemm_nt<1><<<dim3(HH/128, (BB*LL)/128), 256>>>(p_xn, Wv, bv, p_v, BB*LL, HH, DD);
  // 3) EMA scan + omega residual -> g_mx
  ema_k<<<BB*16, 64>>>(delta, alpha, ema_beta, ema_gamma, omega);
  // 4) rmsnorm in place
  rms_norm<<<BB*LL, 256>>>(rms_weight);
  // 5) base = mx @ Wmx^T + bmx
  sgemm_nt<0><<<dim3(BW/128, (BB*LL)/128), 256>>>(p_mx, Wmx, bmx, p_base, BB*LL, BW, DD);
  // 6) S = q@k^T + rel_bias, causal mask
  qk_gemm<<<dim3(LL/128, LL/128, BB), 256>>>(qk_gamma, qk_beta, rel_bias);
  // 7) softmax rows
  softmax_rows<<<BB*LL, 256>>>();
  // 8) hr = (attn @ v) * silu(r)
  av_gemm<<<dim3(HH/128, LL/128, BB), 256>>>();
  // 9) out = x + u*(silu(hx + hr@Wh^T) - x)
  final_gemm<<<dim3(DD/128, (BB*LL)/128), 256>>>(Wh, x, out);
}

// round 6
// speedup vs baseline: 4.5360x; 4.5360x over previous
#include <cuda_runtime.h>
#include <cstdint>
#include <math.h>

// Problem constants
#define BB 8
#define LL 2048
#define DD 1024
#define ZZ 128
#define HH 2048
#define GG 32
#define MP 2048
#define BW 4224   // Z + H + 2D

// ---------------- scratch (device globals; no cudaMalloc allowed) ----------------
__device__ __align__(16) float g_xn[BB*LL*DD];          //  64 MB
__device__ __align__(16) float g_s1[BB*LL*GG];          //   2 MB
__device__ __align__(16) float g_s2[BB*LL*GG];          //   2 MB
__device__ __align__(16) float g_v [BB*LL*HH];          // 128 MB
__device__ __align__(16) float g_vT[BB*HH*LL];          // 128 MB
__device__ __align__(16) float g_mx[BB*LL*DD];          //  64 MB
__device__ __align__(16) float g_base[(size_t)BB*LL*BW];// 277 MB
__device__ __align__(16) float g_S [(size_t)BB*LL*LL];  // 134 MB
__device__ __align__(16) float g_hr[BB*LL*HH];          // 128 MB
__device__ __align__(16) float g_q [BB*LL*ZZ];          //   8 MB
__device__ __align__(16) float g_k [BB*LL*ZZ];          //   8 MB

__device__ __forceinline__ float siluf(float x){ return x/(1.f+__expf(-x)); }
__device__ __forceinline__ float warpMax(float v){
  #pragma unroll
  for(int o=16;o>0;o>>=1) v=fmaxf(v,__shfl_xor_sync(0xffffffffu,v,o));
  return v;
}
__device__ __forceinline__ float warpSum(float v){
  #pragma unroll
  for(int o=16;o>0;o>>=1) v+=__shfl_xor_sync(0xffffffffu,v,o);
  return v;
}
__device__ __forceinline__ uint32_t smem_u32(const void* p){
  uint32_t a;
  asm("{ .reg .u64 t; cvta.to.shared.u64 t, %1; cvt.u32.u64 %0, t; }" : "=r"(a) : "l"(p));
  return a;
}
__device__ __forceinline__ void cpa16(uint32_t dst, const void* src){
  asm volatile("cp.async.cg.shared.global [%0], [%1], 16;" :: "r"(dst), "l"(src));
}
__device__ __forceinline__ uint32_t tf32c(float f){
  uint32_t r; asm("cvt.rna.tf32.f32 %0, %1;" : "=r"(r) : "f"(f)); return r;
}
__device__ __forceinline__ void mma8(float* c, const uint32_t* a, const uint32_t* b){
  asm volatile("mma.sync.aligned.m16n8k8.row.col.f32.tf32.tf32.f32 "
    "{%0,%1,%2,%3}, {%4,%5,%6,%7}, {%8,%9}, {%0,%1,%2,%3};"
    : "+f"(c[0]),"+f"(c[1]),"+f"(c[2]),"+f"(c[3])
    : "r"(a[0]),"r"(a[1]),"r"(a[2]),"r"(a[3]), "r"(b[0]),"r"(b[1]));
}

// ======================= timestep_norm: group sums + scan =======================
__global__ void __launch_bounds__(256) tn_scan(const float* __restrict__ x){
  int bg = blockIdx.x; int b = bg >> 5; int g = bg & 31;
  int t = threadIdx.x;
  float c1[8], c2[8];
  float r1 = 0.f, r2 = 0.f;
  const float* xb = x + (size_t)b*LL*DD + g*32;
  #pragma unroll
  for(int i=0;i<8;i++){
    int l = t*8 + i;
    const float4* q = (const float4*)(xb + (size_t)l*DD);
    float a1=0.f, a2=0.f;
    #pragma unroll
    for(int c=0;c<8;c++){
      float4 f = q[c];
      a1 += f.x+f.y+f.z+f.w;
      a2 += f.x*f.x+f.y*f.y+f.z*f.z+f.w*f.w;
    }
    r1 += a1; r2 += a2;
    c1[i] = r1; c2[i] = r2;
  }
  __shared__ float sm1[256], sm2[256];
  sm1[t]=r1; sm2[t]=r2;
  __syncthreads();
  for(int off=1; off<256; off<<=1){
    float a1=0.f, a2=0.f;
    if(t>=off){ a1=sm1[t-off]; a2=sm2[t-off]; }
    __syncthreads();
    sm1[t]+=a1; sm2[t]+=a2;
    __syncthreads();
  }
  float p1 = (t>0)? sm1[t-1] : 0.f;
  float p2 = (t>0)? sm2[t-1] : 0.f;
  #pragma unroll
  for(int i=0;i<8;i++){
    int l = t*8 + i;
    g_s1[((size_t)b*LL + l)*GG + g] = p1 + c1[i];
    g_s2[((size_t)b*LL + l)*GG + g] = p2 + c2[i];
  }
}

__global__ void __launch_bounds__(256) tn_norm_k(
    const float* __restrict__ x, const float* __restrict__ pm,
    const float* __restrict__ plv, const float* __restrict__ w,
    const float* __restrict__ bias){
  int idx = blockIdx.x*256 + threadIdx.x;
  int d  = idx & (DD-1);
  int bl = idx >> 10;
  int l  = bl & (LL-1);
  int g  = d >> 5;
  float s1 = g_s1[(size_t)bl*GG + g];
  float s2 = g_s2[(size_t)bl*GG + g];
  float cnt = 2.0f + 32.0f*(float)(l+1);
  float pmg = pm[g];
  float pv  = expf(plv[g]);
  float mean = (2.0f*pmg + s1)/cnt;
  float var  = (2.0f*(pv + pmg*pmg) + s2)/cnt - mean*mean;
  float xv = x[idx];
  g_xn[idx] = (xv - mean)*rsqrtf(var + 1e-5f)*w[d] + bias[d];
}

// ======================= multihead EMA: 16-state linear scan =======================
__global__ void __launch_bounds__(64) ema_k(
    const float* __restrict__ delta, const float* __restrict__ alpha,
    const float* __restrict__ ebeta, const float* __restrict__ egam,
    const float* __restrict__ omega){
  int b = blockIdx.x >> 4;
  int d = ((blockIdx.x & 15) << 6) + threadIdx.x;
  float q[16], pb[16], gs[16], s[16];
  #pragma unroll
  for(int n=0;n<16;n++){
    float p = 1.f/(1.f+expf(-delta[d*16+n]));
    float a = 1.f/(1.f+expf(-alpha[d*16+n]));
    q[n]  = 1.f - p*a;
    pb[n] = p*ebeta[d*16+n];
    gs[n] = egam[d*16+n]*0.25f;
    s[n]  = 0.f;
  }
  float om = omega[d];
  const float* xp = g_xn + (size_t)b*LL*DD + d;
  float*       op = g_mx + (size_t)b*LL*DD + d;
  for(int l=0;l<LL;l++){
    float xv = xp[(size_t)l*DD];
    float o0 = om*xv, o1=0.f, o2=0.f, o3=0.f;
    #pragma unroll
    for(int n=0;n<16;n+=4){
      s[n+0] = q[n+0]*s[n+0] + pb[n+0]*xv; o0 += gs[n+0]*s[n+0];
      s[n+1] = q[n+1]*s[n+1] + pb[n+1]*xv; o1 += gs[n+1]*s[n+1];
      s[n+2] = q[n+2]*s[n+2] + pb[n+2]*xv; o2 += gs[n+2]*s[n+2];
      s[n+3] = q[n+3]*s[n+3] + pb[n+3]*xv; o3 += gs[n+3]*s[n+3];
    }
    op[(size_t)l*DD] = (o0+o1)+(o2+o3);
  }
}

// ======================= RMS norm in place on g_mx =======================
__global__ void __launch_bounds__(256) rms_norm(const float* __restrict__ w){
  int row = blockIdx.x;
  float* p = g_mx + (size_t)row*DD;
  int t = threadIdx.x;
  float v[4]; float ss = 0.f;
  #pragma unroll
  for(int j=0;j<4;j++){ v[j] = p[t + 256*j]; ss += v[j]*v[j]; }
  __shared__ float red[8];
  ss = warpSum(ss);
  if((t&31)==0) red[t>>5] = ss;
  __syncthreads();
  if(t<32){
    float a = (t<8)? red[t] : 0.f;
    a = warpSum(a);
    if(t==0) red[0] = a;
  }
  __syncthreads();
  float sc = rsqrtf(red[0]*(1.0f/DD) + 1e-5f);
  #pragma unroll
  for(int j=0;j<4;j++) p[t+256*j] = v[j]*sc*w[t+256*j];
}

// ======================= q/k materialization =======================
__global__ void __launch_bounds__(256) qk_prep(const float* __restrict__ qkg,
                                               const float* __restrict__ qkb){
  int idx = blockIdx.x*256 + threadIdx.x;   // over BB*LL*ZZ
  int bl = idx >> 7, i = idx & 127;
  float zb = g_base[(size_t)bl*BW + DD + i];
  float s = zb/(1.f+__expf(-zb));
  g_q[idx] = (s*qkg[i]      + qkb[i])      * 0.0883883476483184f;
  g_k[idx] =  s*qkg[ZZ+i]   + qkb[ZZ+i];
}

// ======================= V transpose: [b][l][h] -> [b][h][l] =======================
__global__ void __launch_bounds__(256) vT_k(){
  __shared__ float t[32][33];
  int b = blockIdx.z;
  int h0 = blockIdx.x<<5, l0 = blockIdx.y<<5;
  int tx = threadIdx.x & 31, ty = threadIdx.x >> 5;
  const float* src = g_v + (size_t)b*LL*HH;
  float* dst = g_vT + (size_t)b*HH*LL;
  #pragma unroll
  for(int i=0;i<4;i++)
    t[ty+8*i][tx] = src[(size_t)(l0+ty+8*i)*HH + h0 + tx];
  __syncthreads();
  #pragma unroll
  for(int i=0;i<4;i++)
    dst[(size_t)(h0+ty+8*i)*LL + l0 + tx] = t[tx][ty+8*i];
}

// ======================= row softmax on g_S =======================
__global__ void __launch_bounds__(256) softmax_rows(){
  int row = blockIdx.x;
  float* p = g_S + (size_t)row*LL;
  int t = threadIdx.x;
  float v[8];
  float m = -3.0e38f;
  #pragma unroll
  for(int j=0;j<8;j++){ v[j] = p[t + 256*j]; m = fmaxf(m, v[j]); }
  __shared__ float red[8];
  m = warpMax(m);
  if((t&31)==0) red[t>>5] = m;
  __syncthreads();
  if(t<32){
    float a = (t<8)? red[t] : -3.0e38f;
    a = warpMax(a);
    if(t==0) red[0] = a;
  }
  __syncthreads();
  m = red[0];
  __syncthreads();
  float s = 0.f;
  #pragma unroll
  for(int j=0;j<8;j++){ v[j] = __expf(v[j]-m); s += v[j]; }
  s = warpSum(s);
  if((t&31)==0) red[t>>5] = s;
  __syncthreads();
  if(t<32){
    float a = (t<8)? red[t] : 0.f;
    a = warpSum(a);
    if(t==0) red[0] = a;
  }
  __syncthreads();
  float inv = 1.f/red[0];
  #pragma unroll
  for(int j=0;j<8;j++) p[t + 256*j] = v[j]*inv;
}

// ======================= tf32 mma.sync NT GEMM, fused epilogues =======================
// EPI: 0 = +bias (base), 1 = silu(+bias) (v), 2 = qk (+relbias, causal mask),
//      3 = av (*silu(r)), 4 = final (gated output)
// BM=BN=128, BK=32, 256 threads (8 warps: 2 along M x 4 along N, warp tile 64x32)
#define NST 3
#define SPAD 36                   // smem row stride (floats): bank-conflict-free
#define STG_FL (2*128*SPAD)       // floats per stage (A + B)
#define MM_SMEM (NST*STG_FL*4)

template<int EPI>
__global__ void __launch_bounds__(256) mm_mma(
    const float* __restrict__ A, const float* __restrict__ Bw,
    const float* __restrict__ bias, float* __restrict__ C,
    int N, int K, long sAz, long sBz, long sCz, int Mrows,
    const float* __restrict__ xres, const float* __restrict__ relb)
{
  extern __shared__ float sm[];
  const int tid  = threadIdx.x;
  const int wid  = tid >> 5, lane = tid & 31;
  const int wm   = wid & 1, wn = wid >> 1;       // 2 x 4 warp grid
  const int l4   = lane & 3, l2 = lane >> 2;
  const int bm   = blockIdx.y*128, bn = blockIdx.x*128, z = blockIdx.z;

  if (EPI == 2 && bn > bm){   // fully masked block
    float4 m4 = make_float4(-1e30f,-1e30f,-1e30f,-1e30f);
    float* cp = C + (size_t)z*sCz + (size_t)(bm + tid)*N + bn;
    #pragma unroll
    for(int j=0;j<32;j++) ((float4*)cp)[j] = m4;
    return;
  }

  const uint32_t sb = smem_u32(sm);
  int nk = K >> 5;
  if (EPI == 3) nk = (bm + 128) >> 5;   // causal K bound

  const float* Abase = A + (size_t)z*sAz + (size_t)bm*K;
  const float* Bbase = Bw + (size_t)z*sBz + (size_t)bn*K;

  // per-thread load indices: 4 chunks of 16B for A, 4 for B
  int lrow[4], lcb[4];
  #pragma unroll
  for(int i=0;i<4;i++){
    int idx = tid + (i<<8);
    lrow[i] = idx >> 3;
    lcb[i]  = (idx & 7) << 2;   // float offset (multiple of 4)
  }

  auto load_stage = [&](int s){
    uint32_t stA = sb + (uint32_t)(s % NST)*(STG_FL*4);
    uint32_t stB = stA + 128*SPAD*4;
    const float* Ap = Abase + s*32;
    const float* Bp = Bbase + s*32;
    #pragma unroll
    for(int i=0;i<4;i++){
      uint32_t off = (uint32_t)(lrow[i]*SPAD + lcb[i])*4;
      cpa16(stA + off, Ap + (size_t)lrow[i]*K + lcb[i]);
      cpa16(stB + off, Bp + (size_t)lrow[i]*K + lcb[i]);
    }
    asm volatile("cp.async.commit_group;" ::: "memory");
  };

  load_stage(0);
  load_stage(1);

  float c[4][4][4];
  #pragma unroll
  for(int mi=0;mi<4;mi++)
    #pragma unroll
    for(int ni=0;ni<4;ni++)
      #pragma unroll
      for(int r=0;r<4;r++) c[mi][ni][r] = 0.f;

  for(int s=0;s<nk;s++){
    asm volatile("cp.async.wait_group 1;" ::: "memory");
    __syncthreads();
    if (s+2 < nk) load_stage(s+2);
    const float* As_ = sm + (s % NST)*STG_FL;
    const float* Bs_ = As_ + 128*SPAD;
    #pragma unroll
    for(int kk=0;kk<32;kk+=8){
      uint32_t af[4][4], bf[4][2];
      #pragma unroll
      for(int mi=0;mi<4;mi++){
        int r0 = wm*64 + mi*16 + l2;
        af[mi][0] = tf32c(As_[ r0     *SPAD + kk + l4    ]);
        af[mi][1] = tf32c(As_[(r0+8)  *SPAD + kk + l4    ]);
        af[mi][2] = tf32c(As_[ r0     *SPAD + kk + l4 + 4]);
        af[mi][3] = tf32c(As_[(r0+8)  *SPAD + kk + l4 + 4]);
      }
      #pragma unroll
      for(int ni=0;ni<4;ni++){
        int n0 = wn*32 + ni*8 + l2;
        bf[ni][0] = tf32c(Bs_[n0*SPAD + kk + l4    ]);
        bf[ni][1] = tf32c(Bs_[n0*SPAD + kk + l4 + 4]);
      }
      #pragma unroll
      for(int mi=0;mi<4;mi++)
        #pragma unroll
        for(int ni=0;ni<4;ni++)
          mma8(c[mi][ni], af[mi], bf[ni]);
    }
    __syncthreads();
  }

  // ---------------- epilogue ----------------
  #pragma unroll
  for(int mi=0;mi<4;mi++){
    #pragma unroll
    for(int h=0;h<2;h++){
      int row  = bm + wm*64 + mi*16 + l2 + h*8;
      int grow = z*Mrows + row;
      float* cp = C + (size_t)z*sCz + (size_t)row*N;
      #pragma unroll
      for(int ni=0;ni<4;ni++){
        int col = bn + wn*32 + ni*8 + 2*l4;
        float v0 = c[mi][ni][2*h+0];
        float v1 = c[mi][ni][2*h+1];
        if (EPI == 0){ v0 += bias[col]; v1 += bias[col+1]; }
        else if (EPI == 1){
          v0 = siluf(v0 + bias[col]); v1 = siluf(v1 + bias[col+1]);
        } else if (EPI == 2){
          v0 += relb[MP-1 + col   - row];
          v1 += relb[MP-1 + col+1 - row];
          if (col   > row) v0 = -1e30f;
          if (col+1 > row) v1 = -1e30f;
        } else if (EPI == 3){
          const float* rr = g_base + (size_t)grow*BW + (DD+ZZ);
          v0 *= siluf(rr[col]); v1 *= siluf(rr[col+1]);
        } else {
          const float* br = g_base + (size_t)grow*BW;
          float t0 = siluf(br[DD+ZZ+HH+col]   + v0);
          float t1 = siluf(br[DD+ZZ+HH+col+1] + v1);
          float u0 = 1.f/(1.f+__expf(-br[col]));
          float u1 = 1.f/(1.f+__expf(-br[col+1]));
          float x0 = xres[(size_t)grow*DD + col];
          float x1 = xres[(size_t)grow*DD + col+1];
          v0 = x0 + u0*(t0 - x0);
          v1 = x1 + u1*(t1 - x1);
        }
        *(float2*)(cp + col) = make_float2(v0, v1);
      }
    }
  }
}

// ======================= launch =======================
extern "C" void kernel_launch(void* const* d_in, const int* in_sizes, int n_in,
                              void* d_out, int out_size){
  (void)in_sizes; (void)n_in; (void)out_size;
  const float* x          = (const float*)d_in[0];
  const float* prior_mean = (const float*)d_in[1];
  const float* prior_logv = (const float*)d_in[2];
  const float* tn_weight  = (const float*)d_in[3];
  const float* tn_bias    = (const float*)d_in[4];
  const float* delta      = (const float*)d_in[5];
  const float* alpha      = (const float*)d_in[6];
  const float* ema_beta   = (const float*)d_in[7];
  const float* ema_gamma  = (const float*)d_in[8];
  const float* omega      = (const float*)d_in[9];
  const float* rms_weight = (const float*)d_in[10];
  const float* Wv         = (const float*)d_in[11];
  const float* bv         = (const float*)d_in[12];
  const float* Wmx        = (const float*)d_in[13];
  const float* bmx        = (const float*)d_in[14];
  const float* Wh         = (const float*)d_in[15];
  const float* qk_gamma   = (const float*)d_in[16];
  const float* qk_beta    = (const float*)d_in[17];
  const float* rel_bias   = (const float*)d_in[18];
  float* out = (float*)d_out;

  float *p_xn, *p_mx, *p_v, *p_vT, *p_base, *p_S, *p_hr, *p_q, *p_k;
  cudaGetSymbolAddress((void**)&p_xn,   g_xn);
  cudaGetSymbolAddress((void**)&p_mx,   g_mx);
  cudaGetSymbolAddress((void**)&p_v,    g_v);
  cudaGetSymbolAddress((void**)&p_vT,   g_vT);
  cudaGetSymbolAddress((void**)&p_base, g_base);
  cudaGetSymbolAddress((void**)&p_S,    g_S);
  cudaGetSymbolAddress((void**)&p_hr,   g_hr);
  cudaGetSymbolAddress((void**)&p_q,    g_q);
  cudaGetSymbolAddress((void**)&p_k,    g_k);

  cudaFuncSetAttribute(mm_mma<0>, cudaFuncAttributeMaxDynamicSharedMemorySize, MM_SMEM);
  cudaFuncSetAttribute(mm_mma<1>, cudaFuncAttributeMaxDynamicSharedMemorySize, MM_SMEM);
  cudaFuncSetAttribute(mm_mma<2>, cudaFuncAttributeMaxDynamicSharedMemorySize, MM_SMEM);
  cudaFuncSetAttribute(mm_mma<3>, cudaFuncAttributeMaxDynamicSharedMemorySize, MM_SMEM);
  cudaFuncSetAttribute(mm_mma<4>, cudaFuncAttributeMaxDynamicSharedMemorySize, MM_SMEM);

  // 1) timestep norm
  tn_scan<<<BB*GG, 256>>>(x);
  tn_norm_k<<<(BB*LL*DD)/256, 256>>>(x, prior_mean, prior_logv, tn_weight, tn_bias);
  // 2) v = silu(xn @ Wv^T + bv)
  mm_mma<1><<<dim3(HH/128, (BB*LL)/128, 1), 256, MM_SMEM>>>(
      p_xn, Wv, bv, p_v, HH, DD, 0,0,0, BB*LL, nullptr, nullptr);
  // 3) V transpose for the NT av GEMM
  vT_k<<<dim3(HH/32, LL/32, BB), 256>>>();
  // 4) EMA scan + omega residual -> g_mx
  ema_k<<<BB*16, 64>>>(delta, alpha, ema_beta, ema_gamma, omega);
  // 5) rmsnorm in place
  rms_norm<<<BB*LL, 256>>>(rms_weight);
  // 6) base = mx @ Wmx^T + bmx
  mm_mma<0><<<dim3(BW/128, (BB*LL)/128, 1), 256, MM_SMEM>>>(
      p_mx, Wmx, bmx, p_base, BW, DD, 0,0,0, BB*LL, nullptr, nullptr);
  // 7) q/k materialization
  qk_prep<<<(BB*LL*ZZ)/256, 256>>>(qk_gamma, qk_beta);
  // 8) S = q@k^T + rel_bias, causal
  mm_mma<2><<<dim3(LL/128, LL/128, BB), 256, MM_SMEM>>>(
      p_q, p_k, nullptr, p_S, LL, ZZ, (long)LL*ZZ, (long)LL*ZZ, (long)LL*LL, LL,
      nullptr, rel_bias);
  // 9) softmax
  softmax_rows<<<BB*LL, 256>>>();
  // 10) hr = (attn @ v) * silu(r)   [causal-bounded K]
  mm_mma<3><<<dim3(HH/128, LL/128, BB), 256, MM_SMEM>>>(
      p_S, p_vT, nullptr, p_hr, HH, LL, (long)LL*LL, (long)HH*LL, (long)LL*HH, LL,
      nullptr, nullptr);
  // 11) out = x + u*(silu(hx + hr@Wh^T) - x)
  mm_mma<4><<<dim3(DD/128, (BB*LL)/128, 1), 256, MM_SMEM>>>(
      p_hr, Wh, nullptr, out, DD, HH, 0,0,0, BB*LL, x, nullptr);
}